// round 5
// baseline (speedup 1.0000x reference)
#include <cuda_runtime.h>
#include <math.h>

#define KS 11
#define TX_ 32
#define TY_ 64
#define NW 8          // warps per block
#define RY 8
#define HRY 74        // TY_ + 10
#define HRX 42        // TX_ + 10
#define SP 43         // padded float2 row stride for input tile

typedef unsigned long long ull;

__device__ __forceinline__ ull pk2(float lo, float hi) {
    ull r; asm("mov.b64 %0,{%1,%2};" : "=l"(r) : "f"(lo), "f"(hi)); return r;
}
__device__ __forceinline__ void upk2(ull v, float& lo, float& hi) {
    asm("mov.b64 {%0,%1},%2;" : "=f"(lo), "=f"(hi) : "l"(v));
}
__device__ __forceinline__ ull fma2(ull a, ull b, ull c) {
    ull d; asm("fma.rn.f32x2 %0,%1,%2,%3;" : "=l"(d) : "l"(a), "l"(b), "l"(c)); return d;
}
__device__ __forceinline__ ull mul2(ull a, ull b) {
    ull d; asm("mul.rn.f32x2 %0,%1,%2;" : "=l"(d) : "l"(a), "l"(b)); return d;
}

__device__ constexpr float GW[KS] = {
    0.00102836f, 0.00759866f, 0.03600077f, 0.10936069f, 0.21300566f,
    0.26601190f,
    0.21300566f, 0.10936069f, 0.03600077f, 0.00759866f, 0.00102836f
};

__device__ float g_X0[3538944];
__device__ float g_Y0[3538944];
__device__ float g_X1[3538944];
__device__ float g_Y1[3538944];
__device__ float g_acc[5 * 96 * 2];

__global__ void zero_acc_kernel() {
    int i = threadIdx.x;
    if (i < 5 * 96 * 2) g_acc[i] = 0.f;
}

// 4-stream SSIM (s=x+y, d=x-y, ss, dd), packed f32x2.
// Tile 32x64, 256 threads, RY=8. All smem access conflict-free (warp = row).
__global__ __launch_bounds__(256, 3)
void ssim_kernel(const float* __restrict__ X, const float* __restrict__ Y,
                 int W, int OW, int scale)
{
    extern __shared__ char smem[];
    float2 (*sSD)[SP] = (float2 (*)[SP])smem;                     // [HRY][SP]
    float4 (*sH)[TX_] = (float4 (*)[TX_])(smem + HRY * SP * 8);   // [HRY][TX_]
    __shared__ float rs[NW], rc[NW];

    const int tx = threadIdx.x, ty = threadIdx.y;
    const int t = ty * 32 + tx;
    const int x0 = blockIdx.x * TX_, y0 = blockIdx.y * TY_;
    const int bc = blockIdx.z;
    const float* Xb = X + (size_t)bc * W * W;
    const float* Yb = Y + (size_t)bc * W * W;

    // Load input tile with halo (zero-pad OOB; only feeds discarded outputs)
    for (int idx = t; idx < HRY * HRX; idx += 256) {
        int r = idx / HRX, c = idx - r * HRX;
        int gx = x0 + c, gy = y0 + r;
        float xv = 0.f, yv = 0.f;
        if (gx < W && gy < W) {
            size_t o = (size_t)gy * W + gx;
            xv = Xb[o]; yv = Yb[o];
        }
        sSD[r][c] = make_float2(xv + yv, xv - yv);
    }
    __syncthreads();

    ull wpk[KS];
    #pragma unroll
    for (int k = 0; k < KS; k++) wpk[k] = pk2(GW[k], GW[k]);

    // Horizontal blur: warp = one row, lane = col. Conflict-free LDS.64.
    for (int r = ty; r < HRY; r += NW) {
        ull a01 = 0ULL, a23 = 0ULL;
        #pragma unroll
        for (int k = 0; k < KS; k++) {
            float2 v = sSD[r][tx + k];
            ull pv = pk2(v.x, v.y);
            a01 = fma2(pv, wpk[k], a01);
            ull vv = mul2(pv, pv);
            a23 = fma2(vv, wpk[k], a23);
        }
        float b0, b1, b2, b3;
        upk2(a01, b0, b1); upk2(a23, b2, b3);
        sH[r][tx] = make_float4(b0, b1, b2, b3);
    }
    __syncthreads();

    // Vertical blur + SSIM, RY=8 outputs per thread (rolling accumulators)
    ull amu[RY], asg[RY];
    #pragma unroll
    for (int j = 0; j < RY; j++) { amu[j] = 0ULL; asg[j] = 0ULL; }
    const int rbase = ty * RY;
    #pragma unroll
    for (int rr = 0; rr < RY - 1 + KS; rr++) {
        float4 u = sH[rbase + rr][tx];
        ull p01 = pk2(u.x, u.y), p23 = pk2(u.z, u.w);
        #pragma unroll
        for (int j = 0; j < RY; j++) {
            int k = rr - j;
            if (k >= 0 && k < KS) {
                amu[j] = fma2(p01, wpk[k], amu[j]);
                asg[j] = fma2(p23, wpk[k], asg[j]);
            }
        }
    }

    float ssum = 0.f, csum = 0.f;
    const int ox = x0 + tx;
    #pragma unroll
    for (int j = 0; j < RY; j++) {
        int oy = y0 + rbase + j;
        if (ox < OW && oy < OW) {
            float ms, md, bss, bdd;
            upk2(amu[j], ms, md); upk2(asg[j], bss, bdd);
            const float C1 = 6.5025f, C2 = 58.5225f;
            float ms2 = ms * ms, md2 = md * md;
            float musum  = 0.5f * (ms2 + md2);
            float mu2x   = 0.5f * (ms2 - md2);
            float sqsum  = 0.5f * (bss + bdd);
            float xy2    = 0.5f * (bss - bdd);
            float s1s2   = sqsum - musum;
            float sig122 = xy2 - mu2x;
            float cs = (sig122 + C2) / (s1s2 + C2);
            float ss = ((mu2x + C1) / (musum + C1)) * cs;
            ssum += ss; csum += cs;
        }
    }

    #pragma unroll
    for (int off = 16; off; off >>= 1) {
        ssum += __shfl_down_sync(0xffffffffu, ssum, off);
        csum += __shfl_down_sync(0xffffffffu, csum, off);
    }
    if (tx == 0) { rs[ty] = ssum; rc[ty] = csum; }
    __syncthreads();
    if (t == 0) {
        float a = 0.f, b = 0.f;
        #pragma unroll
        for (int i = 0; i < NW; i++) { a += rs[i]; b += rc[i]; }
        atomicAdd(&g_acc[(scale * 96 + bc) * 2 + 0], a);
        atomicAdd(&g_acc[(scale * 96 + bc) * 2 + 1], b);
    }
}

__global__ void pool2_kernel(const float* __restrict__ inA, const float* __restrict__ inB,
                             float* __restrict__ outA, float* __restrict__ outB,
                             int W, int n2)
{
    int i = blockIdx.x * blockDim.x + threadIdx.x;
    if (i >= n2) return;
    const float* in = blockIdx.y ? inB : inA;
    float* out = blockIdx.y ? outB : outA;
    int ow = W >> 1, owh = ow >> 1;
    int bc = i / (ow * owh);
    int rem = i - bc * ow * owh;
    int oy = rem / owh, oxp = rem - oy * owh;
    const float* p = in + (size_t)bc * W * W + (size_t)(2 * oy) * W + 4 * oxp;
    float4 r0 = *(const float4*)p;
    float4 r1 = *(const float4*)(p + W);
    float2 o;
    o.x = 0.25f * (r0.x + r0.y + r1.x + r1.y);
    o.y = 0.25f * (r0.z + r0.w + r1.z + r1.w);
    *(float2*)(out + (size_t)bc * ow * ow + (size_t)oy * ow + 2 * oxp) = o;
}

__global__ void finalize_kernel(float* __restrict__ out) {
    __shared__ float sh[96];
    const int i = threadIdx.x;
    const float wts[5]  = {0.0448f, 0.2856f, 0.3001f, 0.2363f, 0.1333f};
    const float cnts[5] = {374.f * 374.f, 182.f * 182.f, 86.f * 86.f, 38.f * 38.f, 14.f * 14.f};
    if (i < 96) {
        float p = 1.f;
        #pragma unroll
        for (int s = 0; s < 5; s++) {
            int comp = (s < 4) ? 1 : 0;
            float m = g_acc[(s * 96 + i) * 2 + comp] / cnts[s];
            m = fmaxf(m, 0.f);
            p *= powf(m, wts[s]);
        }
        sh[i] = p;
    }
    __syncthreads();
    if (i == 0) {
        float s = 0.f;
        for (int j = 0; j < 96; j++) s += sh[j];
        out[0] = 1.f - s / 96.f;
    }
}

#define SSIM_SMEM (HRY * SP * 8 + HRY * TX_ * 16)

extern "C" void kernel_launch(void* const* d_in, const int* in_sizes, int n_in,
                              void* d_out, int out_size)
{
    const float* X = (const float*)d_in[0];
    const float* Y = (const float*)d_in[1];
    float* out = (float*)d_out;

    static int attr_set = 0;
    if (!attr_set) {
        cudaFuncSetAttribute(ssim_kernel, cudaFuncAttributeMaxDynamicSharedMemorySize, SSIM_SMEM);
        attr_set = 1;
    }

    float *X0, *Y0, *X1, *Y1;
    cudaGetSymbolAddress((void**)&X0, g_X0);
    cudaGetSymbolAddress((void**)&Y0, g_Y0);
    cudaGetSymbolAddress((void**)&X1, g_X1);
    cudaGetSymbolAddress((void**)&Y1, g_Y1);

    zero_acc_kernel<<<1, 960>>>();

    dim3 blk(32, NW);
    auto mkgrid = [](int OW) {
        return dim3((OW + TX_ - 1) / TX_, (OW + TY_ - 1) / TY_, 96);
    };

    ssim_kernel<<<mkgrid(374), blk, SSIM_SMEM>>>(X, Y, 384, 374, 0);

    int n1 = 96 * 192 * 192 / 2;
    pool2_kernel<<<dim3((n1 + 255) / 256, 2), 256>>>(X, Y, X0, Y0, 384, n1);
    ssim_kernel<<<mkgrid(182), blk, SSIM_SMEM>>>(X0, Y0, 192, 182, 1);

    int n2 = 96 * 96 * 96 / 2;
    pool2_kernel<<<dim3((n2 + 255) / 256, 2), 256>>>(X0, Y0, X1, Y1, 192, n2);
    ssim_kernel<<<mkgrid(86), blk, SSIM_SMEM>>>(X1, Y1, 96, 86, 2);

    int n3 = 96 * 48 * 48 / 2;
    pool2_kernel<<<dim3((n3 + 255) / 256, 2), 256>>>(X1, Y1, X0, Y0, 96, n3);
    ssim_kernel<<<mkgrid(38), blk, SSIM_SMEM>>>(X0, Y0, 48, 38, 3);

    int n4 = 96 * 24 * 24 / 2;
    pool2_kernel<<<dim3((n4 + 255) / 256, 2), 256>>>(X0, Y0, X1, Y1, 48, n4);
    ssim_kernel<<<mkgrid(14), blk, SSIM_SMEM>>>(X1, Y1, 24, 14, 4);

    finalize_kernel<<<1, 96>>>(out);
}

// round 6
// speedup vs baseline: 1.4291x; 1.4291x over previous
#include <cuda_runtime.h>
#include <math.h>

#define KS 11
#define TILE 32
#define TYB 8
#define RY 4
#define HR 42   // TILE + 10
#define SP 43   // padded float2 row stride

typedef unsigned long long ull;

__device__ __forceinline__ ull pk2(float lo, float hi) {
    ull r; asm("mov.b64 %0,{%1,%2};" : "=l"(r) : "f"(lo), "f"(hi)); return r;
}
__device__ __forceinline__ void upk2(ull v, float& lo, float& hi) {
    asm("mov.b64 {%0,%1},%2;" : "=f"(lo), "=f"(hi) : "l"(v));
}
__device__ __forceinline__ ull fma2(ull a, ull b, ull c) {
    ull d; asm("fma.rn.f32x2 %0,%1,%2,%3;" : "=l"(d) : "l"(a), "l"(b), "l"(c)); return d;
}
__device__ __forceinline__ ull mul2(ull a, ull b) {
    ull d; asm("mul.rn.f32x2 %0,%1,%2;" : "=l"(d) : "l"(a), "l"(b)); return d;
}
__device__ __forceinline__ ull add2(ull a, ull b) {
    ull d; asm("add.rn.f32x2 %0,%1,%2;" : "=l"(d) : "l"(a), "l"(b)); return d;
}

__device__ constexpr float GW[KS] = {
    0.00102836f, 0.00759866f, 0.03600077f, 0.10936069f, 0.21300566f,
    0.26601190f,
    0.21300566f, 0.10936069f, 0.03600077f, 0.00759866f, 0.00102836f
};

// Pyramid scratch in (s,d) float2 form
__device__ float2 g_P0[3538944];   // up to 192^2 * 96
__device__ float2 g_P1[884736];    // up to 96^2 * 96
__device__ float g_acc[5 * 96 * 2];

__global__ void zero_acc_kernel() {
    int i = threadIdx.x;
    if (i < 5 * 96 * 2) g_acc[i] = 0.f;
}

// 4-stream SSIM (s=x+y, d=x-y, ss, dd), packed f32x2, 32x32 tile, RY=4.
// If SDin != null, input is (s,d) float2; else X,Y float. If SDout != null,
// also emits the 2x2-pooled (s,d) tile for the next scale.
__global__ __launch_bounds__(256)
void ssim_kernel(const float* __restrict__ X, const float* __restrict__ Y,
                 const float2* __restrict__ SDin, float2* __restrict__ SDout,
                 int W, int OW, int scale)
{
    __shared__ float2 sSD[HR][SP];
    __shared__ float4 sH[HR][TILE];
    __shared__ float rs[TYB], rc[TYB];

    const int tx = threadIdx.x, ty = threadIdx.y;
    const int t = ty * 32 + tx;
    const int x0 = blockIdx.x * TILE, y0 = blockIdx.y * TILE;
    const int bc = blockIdx.z;

    // Load input tile with halo (zero-pad OOB; only feeds discarded outputs)
    if (SDin) {
        const float2* Sb = SDin + (size_t)bc * W * W;
        for (int idx = t; idx < HR * HR; idx += 256) {
            int r = idx / HR, c = idx - r * HR;
            int gx = x0 + c, gy = y0 + r;
            float2 v = make_float2(0.f, 0.f);
            if (gx < W && gy < W) v = Sb[(size_t)gy * W + gx];
            sSD[r][c] = v;
        }
    } else {
        const float* Xb = X + (size_t)bc * W * W;
        const float* Yb = Y + (size_t)bc * W * W;
        for (int idx = t; idx < HR * HR; idx += 256) {
            int r = idx / HR, c = idx - r * HR;
            int gx = x0 + c, gy = y0 + r;
            float xv = 0.f, yv = 0.f;
            if (gx < W && gy < W) {
                size_t o = (size_t)gy * W + gx;
                xv = Xb[o]; yv = Yb[o];
            }
            sSD[r][c] = make_float2(xv + yv, xv - yv);
        }
    }
    __syncthreads();

    // Fused 2x2 pool into next-scale (s,d) buffer (linear, commutes with basis)
    if (SDout) {
        int W2 = W >> 1;
        int cx = t & 15, cy = t >> 4;
        int gx2 = (x0 >> 1) + cx, gy2 = (y0 >> 1) + cy;
        if (gx2 < W2 && gy2 < W2) {
            float2 a = sSD[2 * cy][2 * cx],     b = sSD[2 * cy][2 * cx + 1];
            float2 c = sSD[2 * cy + 1][2 * cx], d = sSD[2 * cy + 1][2 * cx + 1];
            float2 o;
            o.x = 0.25f * (a.x + b.x + c.x + d.x);
            o.y = 0.25f * (a.y + b.y + c.y + d.y);
            SDout[(size_t)bc * W2 * W2 + (size_t)gy2 * W2 + gx2] = o;
        }
    }

    ull wpk[KS];
    #pragma unroll
    for (int k = 0; k < KS; k++) wpk[k] = pk2(GW[k], GW[k]);

    // Horizontal blur: warp = row, lane = col; even/odd split accumulator chains
    for (int r = ty; r < HR; r += TYB) {
        ull a01e = 0ULL, a01o = 0ULL, a23e = 0ULL, a23o = 0ULL;
        #pragma unroll
        for (int k = 0; k < KS; k += 2) {
            float2 v = sSD[r][tx + k];
            ull pv = pk2(v.x, v.y);
            a01e = fma2(pv, wpk[k], a01e);
            a23e = fma2(mul2(pv, pv), wpk[k], a23e);
        }
        #pragma unroll
        for (int k = 1; k < KS; k += 2) {
            float2 v = sSD[r][tx + k];
            ull pv = pk2(v.x, v.y);
            a01o = fma2(pv, wpk[k], a01o);
            a23o = fma2(mul2(pv, pv), wpk[k], a23o);
        }
        ull a01 = add2(a01e, a01o), a23 = add2(a23e, a23o);
        float b0, b1, b2, b3;
        upk2(a01, b0, b1); upk2(a23, b2, b3);
        sH[r][tx] = make_float4(b0, b1, b2, b3);
    }
    __syncthreads();

    // Vertical blur + SSIM, RY=4 outputs per thread (rolling accumulators)
    ull amu[RY], asg[RY];
    #pragma unroll
    for (int j = 0; j < RY; j++) { amu[j] = 0ULL; asg[j] = 0ULL; }
    const int rbase = ty * RY;
    #pragma unroll
    for (int rr = 0; rr < RY - 1 + KS; rr++) {
        float4 u = sH[rbase + rr][tx];
        ull p01 = pk2(u.x, u.y), p23 = pk2(u.z, u.w);
        #pragma unroll
        for (int j = 0; j < RY; j++) {
            int k = rr - j;
            if (k >= 0 && k < KS) {
                amu[j] = fma2(p01, wpk[k], amu[j]);
                asg[j] = fma2(p23, wpk[k], asg[j]);
            }
        }
    }

    float ssum = 0.f, csum = 0.f;
    const int ox = x0 + tx;
    #pragma unroll
    for (int j = 0; j < RY; j++) {
        int oy = y0 + rbase + j;
        if (ox < OW && oy < OW) {
            float ms, md, bss, bdd;
            upk2(amu[j], ms, md); upk2(asg[j], bss, bdd);
            const float C1 = 6.5025f, C2 = 58.5225f;
            float ms2 = ms * ms, md2 = md * md;
            float musum  = 0.5f * (ms2 + md2);          // mu1^2 + mu2^2
            float mu2x   = 0.5f * (ms2 - md2);          // 2*mu1*mu2
            float sqsum  = 0.5f * (bss + bdd);          // blur(xx)+blur(yy)
            float xy2    = 0.5f * (bss - bdd);          // 2*blur(xy)
            float s1s2   = sqsum - musum;               // sigma1^2 + sigma2^2
            float sig122 = xy2 - mu2x;                  // 2*sigma12
            float cs = (sig122 + C2) / (s1s2 + C2);
            float ss = ((mu2x + C1) / (musum + C1)) * cs;
            ssum += ss; csum += cs;
        }
    }

    #pragma unroll
    for (int off = 16; off; off >>= 1) {
        ssum += __shfl_down_sync(0xffffffffu, ssum, off);
        csum += __shfl_down_sync(0xffffffffu, csum, off);
    }
    if (tx == 0) { rs[ty] = ssum; rc[ty] = csum; }
    __syncthreads();
    if (t == 0) {
        float a = 0.f, b = 0.f;
        #pragma unroll
        for (int i = 0; i < TYB; i++) { a += rs[i]; b += rc[i]; }
        atomicAdd(&g_acc[(scale * 96 + bc) * 2 + 0], a);
        atomicAdd(&g_acc[(scale * 96 + bc) * 2 + 1], b);
    }
}

__global__ void finalize_kernel(float* __restrict__ out) {
    __shared__ float sh[96];
    const int i = threadIdx.x;
    const float wts[5]  = {0.0448f, 0.2856f, 0.3001f, 0.2363f, 0.1333f};
    const float cnts[5] = {374.f * 374.f, 182.f * 182.f, 86.f * 86.f, 38.f * 38.f, 14.f * 14.f};
    if (i < 96) {
        float p = 1.f;
        #pragma unroll
        for (int s = 0; s < 5; s++) {
            int comp = (s < 4) ? 1 : 0;
            float m = g_acc[(s * 96 + i) * 2 + comp] / cnts[s];
            m = fmaxf(m, 0.f);
            p *= powf(m, wts[s]);
        }
        sh[i] = p;
    }
    __syncthreads();
    if (i == 0) {
        float s = 0.f;
        for (int j = 0; j < 96; j++) s += sh[j];
        out[0] = 1.f - s / 96.f;
    }
}

extern "C" void kernel_launch(void* const* d_in, const int* in_sizes, int n_in,
                              void* d_out, int out_size)
{
    const float* X = (const float*)d_in[0];
    const float* Y = (const float*)d_in[1];
    float* out = (float*)d_out;

    float2 *P0, *P1;
    cudaGetSymbolAddress((void**)&P0, g_P0);
    cudaGetSymbolAddress((void**)&P1, g_P1);

    zero_acc_kernel<<<1, 960>>>();

    dim3 blk(32, TYB);
    auto mkgrid = [](int OW) {
        int g = (OW + TILE - 1) / TILE;
        return dim3(g, g, 96);
    };

    // scale 0: reads X,Y; pools 192^2 (s,d) into P0
    ssim_kernel<<<mkgrid(374), blk>>>(X, Y, nullptr, P0, 384, 374, 0);
    // scale 1: reads P0; pools 96^2 into P1
    ssim_kernel<<<mkgrid(182), blk>>>(nullptr, nullptr, P0, P1, 192, 182, 1);
    // scale 2: reads P1; pools 48^2 into P0 (scale-1 data dead)
    ssim_kernel<<<mkgrid(86), blk>>>(nullptr, nullptr, P1, P0, 96, 86, 2);
    // scale 3: reads P0; pools 24^2 into P1 (scale-2 data dead)
    ssim_kernel<<<mkgrid(38), blk>>>(nullptr, nullptr, P0, P1, 48, 38, 3);
    // scale 4: reads P1; no pool
    ssim_kernel<<<mkgrid(14), blk>>>(nullptr, nullptr, P1, nullptr, 24, 14, 4);

    finalize_kernel<<<1, 96>>>(out);
}